// round 15
// baseline (speedup 1.0000x reference)
#include <cuda_runtime.h>

#define BATCH 128
#define CIN   9
#define T0    2048
#define T1    1024
#define RR    512
#define NNODES 65536
#define ESING 8192
#define NEDGE (ESING + RR)      // 8704 incl. self loops
#define HID   128
#define OUTF  12
#define EMAX  2048              // max edges per 64-node tile (avg ~1088, sd ~31)

// ---------------- f32x2 packed-math helpers (sm_103a FFMA2) ------------------
__device__ __forceinline__ unsigned long long pk2(float lo, float hi) {
    unsigned long long r;
    asm("mov.b64 %0, {%1, %2};" : "=l"(r) : "f"(lo), "f"(hi));
    return r;
}
__device__ __forceinline__ void fma2(unsigned long long& d,
                                     unsigned long long a, unsigned long long b) {
    asm("fma.rn.f32x2 %0, %1, %2, %0;" : "+l"(d) : "l"(a), "l"(b));
}
__device__ __forceinline__ float2 upk2(unsigned long long v) {
    float2 f;
    asm("mov.b64 {%0, %1}, %2;" : "=f"(f.x), "=f"(f.y) : "l"(v));
    return f;
}

// ---------------- scratch ----------------------------------------------------
__device__ __align__(16) float g_tc1[BATCH * 16 * T1];
__device__ __align__(16) float g_nodes[NNODES * 32];
__device__ __align__(16) float g_xa[NNODES * 32];
__device__ __align__(16) float g_h1[NNODES * HID];
__device__ __align__(16) float g_h1a[NNODES * HID];
__device__ float g_meanv[BATCH * HID];

__device__ int   g_cnt[RR];
__device__ int   g_pos[RR];
__device__ float g_dis[RR];
__device__ int   g_ptr[RR + 1];
__device__ int2  g_edge[NEDGE];     // {src*32, weight bits}

// ---------------- graph build: zero / count / scan+self / fill ---------------
__global__ void k_zero() {          // 1 block, 512 thr
    int t = threadIdx.x;
    g_cnt[t] = 0;
    g_pos[t] = 0;
    for (int i = t; i < BATCH * HID; i += RR) g_meanv[i] = 0.f;
}

__global__ void k_count(const int* __restrict__ ei, int etot) {  // 32 x 256
    int e = blockIdx.x * 256 + threadIdx.x;
    atomicAdd(&g_cnt[__ldg(&ei[etot + e])], 1);
}

__global__ void k_scan() {          // 1 block, 512 thr; shfl scan + self loops
    __shared__ int wsum[16];
    int t = threadIdx.x;
    int lane = t & 31, w = t >> 5;
    int deg = g_cnt[t] + 1;
    float dis = rsqrtf((float)deg);
    g_dis[t] = dis;
    int v = deg;
#pragma unroll
    for (int off = 1; off < 32; off <<= 1) {
        int n = __shfl_up_sync(0xffffffffu, v, off);
        if (lane >= off) v += n;
    }
    if (lane == 31) wsum[w] = v;
    __syncthreads();
    if (w == 0) {
        int s = (lane < 16) ? wsum[lane] : 0;
#pragma unroll
        for (int off = 1; off < 16; off <<= 1) {
            int n = __shfl_up_sync(0xffffffffu, s, off);
            if (lane >= off) s += n;
        }
        if (lane < 16) wsum[lane] = s;
    }
    __syncthreads();
    int incl = v + ((w > 0) ? wsum[w - 1] : 0);
    g_ptr[t + 1] = incl;
    if (t == 0) g_ptr[0] = 0;
    g_edge[incl - 1] = make_int2(t * 32, __float_as_int(dis * dis));
}

__global__ void k_fill(const int* __restrict__ ei, int etot) {   // 32 x 256
    int e = blockIdx.x * 256 + threadIdx.x;
    int s = __ldg(&ei[e]);
    int t = __ldg(&ei[etot + e]);
    int k = atomicAdd(&g_pos[t], 1);
    g_edge[__ldg(&g_ptr[t]) + k] =
        make_int2(s * 32, __float_as_int(g_dis[s] * g_dis[t]));
}

// ---------------- conv1: all 16 ocs per block, FFMA2 -------------------------
__global__ void k_conv1(const float* __restrict__ x, const float* __restrict__ w,
                        const float* __restrict__ bias) {
    __shared__ float sx[CIN][516];
    __shared__ float sw[16][CIN][5];
    __shared__ float sb[16];
    int tid = threadIdx.x;
    int og   = tid >> 7;
    int tidp = tid & 127;
    int P0 = blockIdx.x * 256;
    int b  = blockIdx.y;
    int raw0 = 2 * P0 - 2;
    const float* xb = x + (long)b * CIN * T0;
    for (int id = tid; id < CIN * 516; id += 256) {
        int c = id / 516, i = id - c * 516;
        int ti = raw0 + i;
        sx[c][i] = (ti >= 0 && ti < T0) ? xb[c * T0 + ti] : 0.f;
    }
    for (int id = tid; id < 16 * CIN * 5; id += 256)
        ((float*)sw)[id] = w[id];
    if (tid < 16) sb[tid] = bias[tid];
    __syncthreads();

    unsigned long long r01[8], r23[8];
#pragma unroll
    for (int q = 0; q < 8; q++) {
        float bv = sb[og * 8 + q];
        r01[q] = pk2(bv, bv);
        r23[q] = pk2(bv, bv);
    }
#pragma unroll
    for (int c = 0; c < CIN; c++) {
        float v[8];
#pragma unroll
        for (int j = 0; j < 8; j++) v[j] = sx[c][4 * tidp + j];
        unsigned long long pa[7];
#pragma unroll
        for (int j = 0; j < 7; j++) pa[j] = pk2(v[j], v[j + 1]);
#pragma unroll
        for (int q = 0; q < 8; q++) {
#pragma unroll
            for (int k = 0; k < 5; k++) {
                float wv = sw[og * 8 + q][c][k];
                unsigned long long wq = pk2(wv, wv);
                fma2(r01[q], pa[k], wq);
                fma2(r23[q], pa[k + 2], wq);
            }
        }
    }
    int p0 = P0 + 2 * tidp;
#pragma unroll
    for (int q = 0; q < 8; q++) {
        int oc = og * 8 + q;
        float2 f01 = upk2(r01[q]), f23 = upk2(r23[q]);
        float o0 = fmaxf(fmaxf(f01.x, f01.y), 0.f);
        float o1 = fmaxf(fmaxf(f23.x, f23.y), 0.f);
        *(float2*)&g_tc1[((long)b * 16 + oc) * T1 + p0] = make_float2(o0, o1);
    }
}

// ---------------- conv2: all 32 ocs per block (512 thr), FFMA2 ---------------
__global__ void k_conv2(const float* __restrict__ w, const float* __restrict__ bias) {
    __shared__ float sx[16][516];
    __shared__ float sw[32][16][5];
    __shared__ float sb[32];
    int tid  = threadIdx.x;
    int og   = tid >> 7;
    int tidp = tid & 127;
    int P0 = blockIdx.x * 256;
    int b  = blockIdx.y;
    int raw0 = 2 * P0 - 2;
    const float* hb = g_tc1 + (long)b * 16 * T1;
    for (int id = tid; id < 16 * 516; id += 512) {
        int c = id / 516, i = id - c * 516;
        int ti = raw0 + i;
        sx[c][i] = (ti >= 0 && ti < T1) ? hb[c * T1 + ti] : 0.f;
    }
    for (int id = tid; id < 32 * 16 * 5; id += 512)
        ((float*)sw)[id] = w[id];
    if (tid < 32) sb[tid] = bias[tid];
    __syncthreads();

    unsigned long long r01[8], r23[8];
#pragma unroll
    for (int q = 0; q < 8; q++) {
        float bv = sb[og * 8 + q];
        r01[q] = pk2(bv, bv);
        r23[q] = pk2(bv, bv);
    }
#pragma unroll
    for (int c = 0; c < 16; c++) {
        float v[8];
#pragma unroll
        for (int j = 0; j < 8; j++) v[j] = sx[c][4 * tidp + j];
        unsigned long long pa[7];
#pragma unroll
        for (int j = 0; j < 7; j++) pa[j] = pk2(v[j], v[j + 1]);
#pragma unroll
        for (int q = 0; q < 8; q++) {
#pragma unroll
            for (int k = 0; k < 5; k++) {
                float wv = sw[og * 8 + q][c][k];
                unsigned long long wq = pk2(wv, wv);
                fma2(r01[q], pa[k], wq);
                fma2(r23[q], pa[k + 2], wq);
            }
        }
    }
    int p0 = P0 + 2 * tidp;
    long node0 = (long)b * RR + p0;
    float out0[8], out1[8];
#pragma unroll
    for (int q = 0; q < 8; q++) {
        float2 f01 = upk2(r01[q]), f23 = upk2(r23[q]);
        out0[q] = fmaxf(fmaxf(f01.x, f01.y), 0.f);
        out1[q] = fmaxf(fmaxf(f23.x, f23.y), 0.f);
    }
    float4* d0 = (float4*)&g_nodes[node0 * 32 + og * 8];
    float4* d1 = (float4*)&g_nodes[(node0 + 1) * 32 + og * 8];
    d0[0] = make_float4(out0[0], out0[1], out0[2], out0[3]);
    d0[1] = make_float4(out0[4], out0[5], out0[6], out0[7]);
    d1[0] = make_float4(out1[0], out1[1], out1[2], out1[3]);
    d1[1] = make_float4(out1[4], out1[5], out1[6], out1[7]);
}

// ---------------- agg32: 64-node tiles, edge tile in smem, global gather -----
// grid 1024 (8 tiles/sample), 256 thr, warp = node. 16KB smem -> 6+ blocks/SM
__global__ void k_agg32() {
    __shared__ int2 se[EMAX];
    int blk = blockIdx.x;
    int b  = blk >> 3;
    int t0 = (blk & 7) * 64;
    int tid = threadIdx.x;
    int beg0 = __ldg(&g_ptr[t0]);
    int cnt  = __ldg(&g_ptr[t0 + 64]) - beg0;
    for (int id = tid; id < cnt; id += 256)
        se[id] = __ldg(&g_edge[beg0 + id]);
    __syncthreads();
    const float* __restrict__ base = g_nodes + (long)b * RR * 32;
    int warp = tid >> 5, lane = tid & 31;
#pragma unroll
    for (int r = 0; r < 8; r++) {
        int t = t0 + r * 8 + warp;
        int beg = __ldg(&g_ptr[t]) - beg0, end = __ldg(&g_ptr[t + 1]) - beg0;
        float a0 = 0.f, a1 = 0.f, a2 = 0.f, a3 = 0.f;
        int i = beg;
        for (; i + 3 < end; i += 4) {
            int2 e0 = se[i], e1 = se[i + 1], e2 = se[i + 2], e3 = se[i + 3];
            a0 = fmaf(__int_as_float(e0.y), __ldg(&base[e0.x + lane]), a0);
            a1 = fmaf(__int_as_float(e1.y), __ldg(&base[e1.x + lane]), a1);
            a2 = fmaf(__int_as_float(e2.y), __ldg(&base[e2.x + lane]), a2);
            a3 = fmaf(__int_as_float(e3.y), __ldg(&base[e3.x + lane]), a3);
        }
        for (; i < end; i++) {
            int2 e = se[i];
            a0 = fmaf(__int_as_float(e.y), __ldg(&base[e.x + lane]), a0);
        }
        g_xa[((long)b * RR + t) * 32 + lane] = (a0 + a1) + (a2 + a3);
    }
}

// ---------------- agg128: 64-node tiles, all 128 feats per edge (float4/lane) -
// grid 1024, 256 thr, warp = node, lane -> float4 (4 wf/edge = minimum)
__global__ void k_agg128() {
    __shared__ int2 se[EMAX];
    int blk = blockIdx.x;
    int b  = blk >> 3;
    int t0 = (blk & 7) * 64;
    int tid = threadIdx.x;
    int beg0 = __ldg(&g_ptr[t0]);
    int cnt  = __ldg(&g_ptr[t0 + 64]) - beg0;
    for (int id = tid; id < cnt; id += 256)
        se[id] = __ldg(&g_edge[beg0 + id]);
    __syncthreads();
    const float4* __restrict__ base4 = (const float4*)(g_h1 + (long)b * RR * HID);
    int warp = tid >> 5, lane = tid & 31;
#pragma unroll
    for (int r = 0; r < 8; r++) {
        int t = t0 + r * 8 + warp;
        int beg = __ldg(&g_ptr[t]) - beg0, end = __ldg(&g_ptr[t + 1]) - beg0;
        float4 s0 = make_float4(0.f, 0.f, 0.f, 0.f);
        float4 s1 = make_float4(0.f, 0.f, 0.f, 0.f);
        int i = beg;
        for (; i + 1 < end; i += 2) {
            int2 e0 = se[i], e1 = se[i + 1];
            float w0 = __int_as_float(e0.y), w1 = __int_as_float(e1.y);
            float4 v0 = __ldg(&base4[e0.x + lane]);
            float4 v1 = __ldg(&base4[e1.x + lane]);
            s0.x = fmaf(w0, v0.x, s0.x); s0.y = fmaf(w0, v0.y, s0.y);
            s0.z = fmaf(w0, v0.z, s0.z); s0.w = fmaf(w0, v0.w, s0.w);
            s1.x = fmaf(w1, v1.x, s1.x); s1.y = fmaf(w1, v1.y, s1.y);
            s1.z = fmaf(w1, v1.z, s1.z); s1.w = fmaf(w1, v1.w, s1.w);
        }
        if (i < end) {
            int2 e = se[i];
            float w = __int_as_float(e.y);
            float4 v = __ldg(&base4[e.x + lane]);
            s0.x = fmaf(w, v.x, s0.x); s0.y = fmaf(w, v.y, s0.y);
            s0.z = fmaf(w, v.z, s0.z); s0.w = fmaf(w, v.w, s0.w);
        }
        float4 o = make_float4(s0.x + s1.x, s0.y + s1.y, s0.z + s1.z, s0.w + s1.w);
        ((float4*)(g_h1a + ((long)b * RR + t) * HID))[lane] = o;
    }
}

// ---- permuted W staging: ws2[k][m*16+cc] = (W[k][cc+32m], W[k][cc+16+32m]) --
__device__ __forceinline__ void stage_w_perm(float2 (*ws2)[64],
                                             const float* __restrict__ Wrow0,
                                             int tid, int nthr) {
    for (int id = tid; id < 1024; id += nthr) {
        int kk = id >> 5, c4 = id & 31;
        float4 v = *(const float4*)(Wrow0 + kk * HID + c4 * 4);
        int cbase = c4 * 4;
        float vv[4] = {v.x, v.y, v.z, v.w};
#pragma unroll
        for (int e = 0; e < 4; e++) {
            int c = cbase + e;
            int m = c >> 5, h = (c >> 4) & 1, cc = c & 15;
            ((float*)&ws2[kk][m * 16 + cc])[h] = vv[e];
        }
    }
}

// ---------------- GEMM1: [N,32]@[32,128] + bias, relu, FFMA2 -----------------
__global__ void k_gemm1(const float* __restrict__ W, const float* __restrict__ bias) {
    __shared__ float as[128][33];
    __shared__ float2 ws2[32][64];
    int tid = threadIdx.x;
    long rowBase = (long)blockIdx.x * 128;
    for (int id = tid; id < 1024; id += 256) {
        int r = id >> 3, k4 = id & 7;
        float4 v = *(const float4*)(g_xa + (rowBase + r) * 32 + k4 * 4);
        as[r][k4 * 4 + 0] = v.x; as[r][k4 * 4 + 1] = v.y;
        as[r][k4 * 4 + 2] = v.z; as[r][k4 * 4 + 3] = v.w;
    }
    stage_w_perm(ws2, W, tid, 256);
    __syncthreads();
    int rg = tid >> 4, cg = tid & 15, row0 = rg * 8;
    unsigned long long acc2[8][4];
#pragma unroll
    for (int i = 0; i < 8; i++)
#pragma unroll
        for (int m = 0; m < 4; m++) acc2[i][m] = 0ULL;
#pragma unroll
    for (int k = 0; k < 32; k++) {
        unsigned long long ap[8], bp[4];
#pragma unroll
        for (int i = 0; i < 8; i++) {
            float a = as[row0 + i][k];
            ap[i] = pk2(a, a);
        }
#pragma unroll
        for (int m = 0; m < 4; m++)
            bp[m] = *(const unsigned long long*)&ws2[k][m * 16 + cg];
#pragma unroll
        for (int i = 0; i < 8; i++)
#pragma unroll
            for (int m = 0; m < 4; m++) fma2(acc2[i][m], ap[i], bp[m]);
    }
#pragma unroll
    for (int i = 0; i < 8; i++)
#pragma unroll
        for (int m = 0; m < 4; m++) {
            float2 f = upk2(acc2[i][m]);
            int c0 = cg + 32 * m, c1 = cg + 16 + 32 * m;
            g_h1[(rowBase + row0 + i) * HID + c0] = fmaxf(f.x + bias[c0], 0.f);
            g_h1[(rowBase + row0 + i) * HID + c1] = fmaxf(f.y + bias[c1], 0.f);
        }
}

// ---------------- GEMM2 + bias + relu + mean, FFMA2 --------------------------
__global__ void k_gemm2m(const float* __restrict__ W, const float* __restrict__ bias) {
    __shared__ float as[128][33];
    __shared__ float2 ws2[32][64];
    __shared__ float smean[HID];
    int tid = threadIdx.x;
    long rowBase = (long)blockIdx.x * 128;
    int b = blockIdx.x >> 2;
    int rg = tid >> 4, cg = tid & 15, row0 = rg * 8;
    unsigned long long acc2[8][4];
#pragma unroll
    for (int i = 0; i < 8; i++)
#pragma unroll
        for (int m = 0; m < 4; m++) acc2[i][m] = 0ULL;
    for (int kc = 0; kc < 4; kc++) {
        __syncthreads();
        for (int id = tid; id < 1024; id += 256) {
            int r = id >> 3, k4 = id & 7;
            float4 v = *(const float4*)(g_h1a + (rowBase + r) * HID + kc * 32 + k4 * 4);
            as[r][k4 * 4 + 0] = v.x; as[r][k4 * 4 + 1] = v.y;
            as[r][k4 * 4 + 2] = v.z; as[r][k4 * 4 + 3] = v.w;
        }
        stage_w_perm(ws2, W + kc * 32 * HID, tid, 256);
        __syncthreads();
#pragma unroll
        for (int k = 0; k < 32; k++) {
            unsigned long long ap[8], bp[4];
#pragma unroll
            for (int i = 0; i < 8; i++) {
                float a = as[row0 + i][k];
                ap[i] = pk2(a, a);
            }
#pragma unroll
            for (int m = 0; m < 4; m++)
                bp[m] = *(const unsigned long long*)&ws2[k][m * 16 + cg];
#pragma unroll
            for (int i = 0; i < 8; i++)
#pragma unroll
                for (int m = 0; m < 4; m++) fma2(acc2[i][m], ap[i], bp[m]);
        }
    }
    if (tid < HID) smean[tid] = 0.f;
    __syncthreads();
#pragma unroll
    for (int m = 0; m < 4; m++) {
        int c0 = cg + 32 * m, c1 = cg + 16 + 32 * m;
        float b0 = bias[c0], b1 = bias[c1];
        float s0 = 0.f, s1 = 0.f;
#pragma unroll
        for (int i = 0; i < 8; i++) {
            float2 f = upk2(acc2[i][m]);
            s0 += fmaxf(f.x + b0, 0.f);
            s1 += fmaxf(f.y + b1, 0.f);
        }
        atomicAdd(&smean[c0], s0);
        atomicAdd(&smean[c1], s1);
    }
    __syncthreads();
    if (tid < HID) atomicAdd(&g_meanv[b * HID + tid], smean[tid] * (1.0f / RR));
}

// ---------------- fc ---------------------------------------------------------
__global__ void k_fc(const float* __restrict__ fw, const float* __restrict__ fb,
                     float* __restrict__ out) {
    int b = blockIdx.x;
    __shared__ float m[HID];
    m[threadIdx.x] = g_meanv[b * HID + threadIdx.x];
    __syncthreads();
    if (threadIdx.x < OUTF) {
        float acc = fb[threadIdx.x];
#pragma unroll
        for (int f = 0; f < HID; f++)
            acc = fmaf(m[f], fw[f * OUTF + threadIdx.x], acc);
        out[b * OUTF + threadIdx.x] = acc;
    }
}

// ---------------- launch ------------------------------------------------------
extern "C" void kernel_launch(void* const* d_in, const int* in_sizes, int n_in,
                              void* d_out, int out_size) {
    const float* x   = (const float*)d_in[0];
    const int*   ei  = (const int*)  d_in[1];
    const float* c1w = (const float*)d_in[2];
    const float* c1b = (const float*)d_in[3];
    const float* c2w = (const float*)d_in[4];
    const float* c2b = (const float*)d_in[5];
    const float* g1w = (const float*)d_in[6];
    const float* g1b = (const float*)d_in[7];
    const float* g2w = (const float*)d_in[8];
    const float* g2b = (const float*)d_in[9];
    const float* fw  = (const float*)d_in[10];
    const float* fb  = (const float*)d_in[11];
    float* out = (float*)d_out;
    int etot = in_sizes[1] / 2;

    k_zero<<<1, RR>>>();
    k_count<<<ESING / 256, 256>>>(ei, etot);
    k_scan<<<1, RR>>>();
    k_fill<<<ESING / 256, 256>>>(ei, etot);
    k_conv1<<<dim3(T1 / 256, BATCH), 256>>>(x, c1w, c1b);
    k_conv2<<<dim3(RR / 256, BATCH), 512>>>(c2w, c2b);
    k_agg32<<<NNODES / 64, 256>>>();                 // 64-node edge tiles
    k_gemm1<<<NNODES / 128, 256>>>(g1w, g1b);
    k_agg128<<<NNODES / 64, 256>>>();                // 64-node edge tiles
    k_gemm2m<<<NNODES / 128, 256>>>(g2w, g2b);
    k_fc<<<BATCH, HID>>>(fw, fb, out);
}

// round 16
// speedup vs baseline: 1.5627x; 1.5627x over previous
#include <cuda_runtime.h>

#define BATCH 128
#define CIN   9
#define T0    2048
#define T1    1024
#define RR    512
#define NNODES 65536
#define ESING 8192
#define NEDGE (ESING + RR)      // 8704 incl. self loops
#define HID   128
#define OUTF  12

// ---------------- f32x2 packed-math helpers (sm_103a FFMA2) ------------------
__device__ __forceinline__ unsigned long long pk2(float lo, float hi) {
    unsigned long long r;
    asm("mov.b64 %0, {%1, %2};" : "=l"(r) : "f"(lo), "f"(hi));
    return r;
}
__device__ __forceinline__ void fma2(unsigned long long& d,
                                     unsigned long long a, unsigned long long b) {
    asm("fma.rn.f32x2 %0, %1, %2, %0;" : "+l"(d) : "l"(a), "l"(b));
}
__device__ __forceinline__ float2 upk2(unsigned long long v) {
    float2 f;
    asm("mov.b64 {%0, %1}, %2;" : "=f"(f.x), "=f"(f.y) : "l"(v));
    return f;
}

// ---------------- scratch ----------------------------------------------------
__device__ __align__(16) float g_tc1[BATCH * 16 * T1];
__device__ __align__(16) float g_nodes[NNODES * 32];
__device__ __align__(16) float g_xa[NNODES * 32];
__device__ __align__(16) float g_h1[NNODES * HID];
__device__ __align__(16) float g_h1a[NNODES * HID];
__device__ float g_meanv[BATCH * HID];

__device__ int   g_cnt[RR];
__device__ int   g_pos[RR];
__device__ float g_dis[RR];
__device__ int   g_ptr[RR + 1];
__device__ int2  g_edge[NEDGE];     // {src*32, weight bits}

// ---------------- graph build: zero / count / scan+self / fill ---------------
__global__ void k_zero() {          // 1 block, 512 thr
    int t = threadIdx.x;
    g_cnt[t] = 0;
    g_pos[t] = 0;
    for (int i = t; i < BATCH * HID; i += RR) g_meanv[i] = 0.f;
}

__global__ void k_count(const int* __restrict__ ei, int etot) {  // 32 x 256
    int e = blockIdx.x * 256 + threadIdx.x;
    atomicAdd(&g_cnt[__ldg(&ei[etot + e])], 1);
}

__global__ void k_scan() {          // 1 block, 512 thr; shfl scan + self loops
    __shared__ int wsum[16];
    int t = threadIdx.x;
    int lane = t & 31, w = t >> 5;
    int deg = g_cnt[t] + 1;
    float dis = rsqrtf((float)deg);
    g_dis[t] = dis;
    int v = deg;
#pragma unroll
    for (int off = 1; off < 32; off <<= 1) {
        int n = __shfl_up_sync(0xffffffffu, v, off);
        if (lane >= off) v += n;
    }
    if (lane == 31) wsum[w] = v;
    __syncthreads();
    if (w == 0) {
        int s = (lane < 16) ? wsum[lane] : 0;
#pragma unroll
        for (int off = 1; off < 16; off <<= 1) {
            int n = __shfl_up_sync(0xffffffffu, s, off);
            if (lane >= off) s += n;
        }
        if (lane < 16) wsum[lane] = s;
    }
    __syncthreads();
    int incl = v + ((w > 0) ? wsum[w - 1] : 0);
    g_ptr[t + 1] = incl;
    if (t == 0) g_ptr[0] = 0;
    g_edge[incl - 1] = make_int2(t * 32, __float_as_int(dis * dis));
}

__global__ void k_fill(const int* __restrict__ ei, int etot) {   // 32 x 256
    int e = blockIdx.x * 256 + threadIdx.x;
    int s = __ldg(&ei[e]);
    int t = __ldg(&ei[etot + e]);
    int k = atomicAdd(&g_pos[t], 1);
    g_edge[__ldg(&g_ptr[t]) + k] =
        make_int2(s * 32, __float_as_int(g_dis[s] * g_dis[t]));
}

// ---------------- conv1: all 16 ocs per block, FFMA2 -------------------------
__global__ void k_conv1(const float* __restrict__ x, const float* __restrict__ w,
                        const float* __restrict__ bias) {
    __shared__ float sx[CIN][516];
    __shared__ float sw[16][CIN][5];
    __shared__ float sb[16];
    int tid = threadIdx.x;
    int og   = tid >> 7;
    int tidp = tid & 127;
    int P0 = blockIdx.x * 256;
    int b  = blockIdx.y;
    int raw0 = 2 * P0 - 2;
    const float* xb = x + (long)b * CIN * T0;
    for (int id = tid; id < CIN * 516; id += 256) {
        int c = id / 516, i = id - c * 516;
        int ti = raw0 + i;
        sx[c][i] = (ti >= 0 && ti < T0) ? xb[c * T0 + ti] : 0.f;
    }
    for (int id = tid; id < 16 * CIN * 5; id += 256)
        ((float*)sw)[id] = w[id];
    if (tid < 16) sb[tid] = bias[tid];
    __syncthreads();

    unsigned long long r01[8], r23[8];
#pragma unroll
    for (int q = 0; q < 8; q++) {
        float bv = sb[og * 8 + q];
        r01[q] = pk2(bv, bv);
        r23[q] = pk2(bv, bv);
    }
#pragma unroll
    for (int c = 0; c < CIN; c++) {
        float v[8];
#pragma unroll
        for (int j = 0; j < 8; j++) v[j] = sx[c][4 * tidp + j];
        unsigned long long pa[7];
#pragma unroll
        for (int j = 0; j < 7; j++) pa[j] = pk2(v[j], v[j + 1]);
#pragma unroll
        for (int q = 0; q < 8; q++) {
#pragma unroll
            for (int k = 0; k < 5; k++) {
                float wv = sw[og * 8 + q][c][k];
                unsigned long long wq = pk2(wv, wv);
                fma2(r01[q], pa[k], wq);
                fma2(r23[q], pa[k + 2], wq);
            }
        }
    }
    int p0 = P0 + 2 * tidp;
#pragma unroll
    for (int q = 0; q < 8; q++) {
        int oc = og * 8 + q;
        float2 f01 = upk2(r01[q]), f23 = upk2(r23[q]);
        float o0 = fmaxf(fmaxf(f01.x, f01.y), 0.f);
        float o1 = fmaxf(fmaxf(f23.x, f23.y), 0.f);
        *(float2*)&g_tc1[((long)b * 16 + oc) * T1 + p0] = make_float2(o0, o1);
    }
}

// ---------------- conv2: all 32 ocs per block (512 thr), FFMA2 ---------------
__global__ void k_conv2(const float* __restrict__ w, const float* __restrict__ bias) {
    __shared__ float sx[16][516];
    __shared__ float sw[32][16][5];
    __shared__ float sb[32];
    int tid  = threadIdx.x;
    int og   = tid >> 7;
    int tidp = tid & 127;
    int P0 = blockIdx.x * 256;
    int b  = blockIdx.y;
    int raw0 = 2 * P0 - 2;
    const float* hb = g_tc1 + (long)b * 16 * T1;
    for (int id = tid; id < 16 * 516; id += 512) {
        int c = id / 516, i = id - c * 516;
        int ti = raw0 + i;
        sx[c][i] = (ti >= 0 && ti < T1) ? hb[c * T1 + ti] : 0.f;
    }
    for (int id = tid; id < 32 * 16 * 5; id += 512)
        ((float*)sw)[id] = w[id];
    if (tid < 32) sb[tid] = bias[tid];
    __syncthreads();

    unsigned long long r01[8], r23[8];
#pragma unroll
    for (int q = 0; q < 8; q++) {
        float bv = sb[og * 8 + q];
        r01[q] = pk2(bv, bv);
        r23[q] = pk2(bv, bv);
    }
#pragma unroll
    for (int c = 0; c < 16; c++) {
        float v[8];
#pragma unroll
        for (int j = 0; j < 8; j++) v[j] = sx[c][4 * tidp + j];
        unsigned long long pa[7];
#pragma unroll
        for (int j = 0; j < 7; j++) pa[j] = pk2(v[j], v[j + 1]);
#pragma unroll
        for (int q = 0; q < 8; q++) {
#pragma unroll
            for (int k = 0; k < 5; k++) {
                float wv = sw[og * 8 + q][c][k];
                unsigned long long wq = pk2(wv, wv);
                fma2(r01[q], pa[k], wq);
                fma2(r23[q], pa[k + 2], wq);
            }
        }
    }
    int p0 = P0 + 2 * tidp;
    long node0 = (long)b * RR + p0;
    float out0[8], out1[8];
#pragma unroll
    for (int q = 0; q < 8; q++) {
        float2 f01 = upk2(r01[q]), f23 = upk2(r23[q]);
        out0[q] = fmaxf(fmaxf(f01.x, f01.y), 0.f);
        out1[q] = fmaxf(fmaxf(f23.x, f23.y), 0.f);
    }
    float4* d0 = (float4*)&g_nodes[node0 * 32 + og * 8];
    float4* d1 = (float4*)&g_nodes[(node0 + 1) * 32 + og * 8];
    d0[0] = make_float4(out0[0], out0[1], out0[2], out0[3]);
    d0[1] = make_float4(out0[4], out0[5], out0[6], out0[7]);
    d1[0] = make_float4(out1[0], out1[1], out1[2], out1[3]);
    d1[1] = make_float4(out1[4], out1[5], out1[6], out1[7]);
}

// ---------------- agg32: NO staging, high occupancy, warp = node -------------
// grid NNODES/8, 256 thr, 0 smem -> full occupancy; gathers straight from L1/L2
__global__ void k_agg32() {
    int tid = threadIdx.x;
    int node = blockIdx.x * 8 + (tid >> 5);
    int lane = tid & 31;
    int b = node >> 9, t = node & (RR - 1);
    const float* __restrict__ base = g_nodes + (long)b * RR * 32;
    int beg = __ldg(&g_ptr[t]), end = __ldg(&g_ptr[t + 1]);
    float a0 = 0.f, a1 = 0.f, a2 = 0.f, a3 = 0.f;
    int i = beg;
    for (; i + 3 < end; i += 4) {
        int2 e0 = __ldg(&g_edge[i]);
        int2 e1 = __ldg(&g_edge[i + 1]);
        int2 e2 = __ldg(&g_edge[i + 2]);
        int2 e3 = __ldg(&g_edge[i + 3]);
        a0 = fmaf(__int_as_float(e0.y), __ldg(&base[e0.x + lane]), a0);
        a1 = fmaf(__int_as_float(e1.y), __ldg(&base[e1.x + lane]), a1);
        a2 = fmaf(__int_as_float(e2.y), __ldg(&base[e2.x + lane]), a2);
        a3 = fmaf(__int_as_float(e3.y), __ldg(&base[e3.x + lane]), a3);
    }
    for (; i < end; i++) {
        int2 e = __ldg(&g_edge[i]);
        a0 = fmaf(__int_as_float(e.y), __ldg(&base[e.x + lane]), a0);
    }
    g_xa[(long)node * 32 + lane] = (a0 + a1) + (a2 + a3);
}

// ---------------- agg128: NO staging, warp = node, float4 per lane -----------
// grid NNODES/8, 256 thr, 0 smem; 4 wavefronts per edge (minimum possible)
__global__ void k_agg128() {
    int tid = threadIdx.x;
    int node = blockIdx.x * 8 + (tid >> 5);
    int lane = tid & 31;
    int b = node >> 9, t = node & (RR - 1);
    const float4* __restrict__ base4 = (const float4*)(g_h1 + (long)b * RR * HID);
    int beg = __ldg(&g_ptr[t]), end = __ldg(&g_ptr[t + 1]);
    float4 s0 = make_float4(0.f, 0.f, 0.f, 0.f);
    float4 s1 = make_float4(0.f, 0.f, 0.f, 0.f);
    float4 s2 = make_float4(0.f, 0.f, 0.f, 0.f);
    float4 s3 = make_float4(0.f, 0.f, 0.f, 0.f);
    int i = beg;
    for (; i + 3 < end; i += 4) {
        int2 e0 = __ldg(&g_edge[i]);
        int2 e1 = __ldg(&g_edge[i + 1]);
        int2 e2 = __ldg(&g_edge[i + 2]);
        int2 e3 = __ldg(&g_edge[i + 3]);
        float w0 = __int_as_float(e0.y), w1 = __int_as_float(e1.y);
        float w2 = __int_as_float(e2.y), w3 = __int_as_float(e3.y);
        float4 v0 = __ldg(&base4[e0.x + lane]);
        float4 v1 = __ldg(&base4[e1.x + lane]);
        float4 v2 = __ldg(&base4[e2.x + lane]);
        float4 v3 = __ldg(&base4[e3.x + lane]);
        s0.x = fmaf(w0, v0.x, s0.x); s0.y = fmaf(w0, v0.y, s0.y);
        s0.z = fmaf(w0, v0.z, s0.z); s0.w = fmaf(w0, v0.w, s0.w);
        s1.x = fmaf(w1, v1.x, s1.x); s1.y = fmaf(w1, v1.y, s1.y);
        s1.z = fmaf(w1, v1.z, s1.z); s1.w = fmaf(w1, v1.w, s1.w);
        s2.x = fmaf(w2, v2.x, s2.x); s2.y = fmaf(w2, v2.y, s2.y);
        s2.z = fmaf(w2, v2.z, s2.z); s2.w = fmaf(w2, v2.w, s2.w);
        s3.x = fmaf(w3, v3.x, s3.x); s3.y = fmaf(w3, v3.y, s3.y);
        s3.z = fmaf(w3, v3.z, s3.z); s3.w = fmaf(w3, v3.w, s3.w);
    }
    for (; i < end; i++) {
        int2 e = __ldg(&g_edge[i]);
        float w = __int_as_float(e.y);
        float4 v = __ldg(&base4[e.x + lane]);
        s0.x = fmaf(w, v.x, s0.x); s0.y = fmaf(w, v.y, s0.y);
        s0.z = fmaf(w, v.z, s0.z); s0.w = fmaf(w, v.w, s0.w);
    }
    float4 o;
    o.x = (s0.x + s1.x) + (s2.x + s3.x);
    o.y = (s0.y + s1.y) + (s2.y + s3.y);
    o.z = (s0.z + s1.z) + (s2.z + s3.z);
    o.w = (s0.w + s1.w) + (s2.w + s3.w);
    ((float4*)(g_h1a + (long)node * HID))[lane] = o;
}

// ---- permuted W staging: ws2[k][m*16+cc] = (W[k][cc+32m], W[k][cc+16+32m]) --
__device__ __forceinline__ void stage_w_perm(float2 (*ws2)[64],
                                             const float* __restrict__ Wrow0,
                                             int tid, int nthr) {
    for (int id = tid; id < 1024; id += nthr) {
        int kk = id >> 5, c4 = id & 31;
        float4 v = *(const float4*)(Wrow0 + kk * HID + c4 * 4);
        int cbase = c4 * 4;
        float vv[4] = {v.x, v.y, v.z, v.w};
#pragma unroll
        for (int e = 0; e < 4; e++) {
            int c = cbase + e;
            int m = c >> 5, h = (c >> 4) & 1, cc = c & 15;
            ((float*)&ws2[kk][m * 16 + cc])[h] = vv[e];
        }
    }
}

// ---------------- GEMM1: [N,32]@[32,128] + bias, relu, FFMA2 -----------------
__global__ void k_gemm1(const float* __restrict__ W, const float* __restrict__ bias) {
    __shared__ float as[128][33];
    __shared__ float2 ws2[32][64];
    int tid = threadIdx.x;
    long rowBase = (long)blockIdx.x * 128;
    for (int id = tid; id < 1024; id += 256) {
        int r = id >> 3, k4 = id & 7;
        float4 v = *(const float4*)(g_xa + (rowBase + r) * 32 + k4 * 4);
        as[r][k4 * 4 + 0] = v.x; as[r][k4 * 4 + 1] = v.y;
        as[r][k4 * 4 + 2] = v.z; as[r][k4 * 4 + 3] = v.w;
    }
    stage_w_perm(ws2, W, tid, 256);
    __syncthreads();
    int rg = tid >> 4, cg = tid & 15, row0 = rg * 8;
    unsigned long long acc2[8][4];
#pragma unroll
    for (int i = 0; i < 8; i++)
#pragma unroll
        for (int m = 0; m < 4; m++) acc2[i][m] = 0ULL;
#pragma unroll
    for (int k = 0; k < 32; k++) {
        unsigned long long ap[8], bp[4];
#pragma unroll
        for (int i = 0; i < 8; i++) {
            float a = as[row0 + i][k];
            ap[i] = pk2(a, a);
        }
#pragma unroll
        for (int m = 0; m < 4; m++)
            bp[m] = *(const unsigned long long*)&ws2[k][m * 16 + cg];
#pragma unroll
        for (int i = 0; i < 8; i++)
#pragma unroll
            for (int m = 0; m < 4; m++) fma2(acc2[i][m], ap[i], bp[m]);
    }
#pragma unroll
    for (int i = 0; i < 8; i++)
#pragma unroll
        for (int m = 0; m < 4; m++) {
            float2 f = upk2(acc2[i][m]);
            int c0 = cg + 32 * m, c1 = cg + 16 + 32 * m;
            g_h1[(rowBase + row0 + i) * HID + c0] = fmaxf(f.x + bias[c0], 0.f);
            g_h1[(rowBase + row0 + i) * HID + c1] = fmaxf(f.y + bias[c1], 0.f);
        }
}

// ---------------- GEMM2 + bias + relu + mean, FFMA2 --------------------------
__global__ void k_gemm2m(const float* __restrict__ W, const float* __restrict__ bias) {
    __shared__ float as[128][33];
    __shared__ float2 ws2[32][64];
    __shared__ float smean[HID];
    int tid = threadIdx.x;
    long rowBase = (long)blockIdx.x * 128;
    int b = blockIdx.x >> 2;
    int rg = tid >> 4, cg = tid & 15, row0 = rg * 8;
    unsigned long long acc2[8][4];
#pragma unroll
    for (int i = 0; i < 8; i++)
#pragma unroll
        for (int m = 0; m < 4; m++) acc2[i][m] = 0ULL;
    for (int kc = 0; kc < 4; kc++) {
        __syncthreads();
        for (int id = tid; id < 1024; id += 256) {
            int r = id >> 3, k4 = id & 7;
            float4 v = *(const float4*)(g_h1a + (rowBase + r) * HID + kc * 32 + k4 * 4);
            as[r][k4 * 4 + 0] = v.x; as[r][k4 * 4 + 1] = v.y;
            as[r][k4 * 4 + 2] = v.z; as[r][k4 * 4 + 3] = v.w;
        }
        stage_w_perm(ws2, W + kc * 32 * HID, tid, 256);
        __syncthreads();
#pragma unroll
        for (int k = 0; k < 32; k++) {
            unsigned long long ap[8], bp[4];
#pragma unroll
            for (int i = 0; i < 8; i++) {
                float a = as[row0 + i][k];
                ap[i] = pk2(a, a);
            }
#pragma unroll
            for (int m = 0; m < 4; m++)
                bp[m] = *(const unsigned long long*)&ws2[k][m * 16 + cg];
#pragma unroll
            for (int i = 0; i < 8; i++)
#pragma unroll
                for (int m = 0; m < 4; m++) fma2(acc2[i][m], ap[i], bp[m]);
        }
    }
    if (tid < HID) smean[tid] = 0.f;
    __syncthreads();
#pragma unroll
    for (int m = 0; m < 4; m++) {
        int c0 = cg + 32 * m, c1 = cg + 16 + 32 * m;
        float b0 = bias[c0], b1 = bias[c1];
        float s0 = 0.f, s1 = 0.f;
#pragma unroll
        for (int i = 0; i < 8; i++) {
            float2 f = upk2(acc2[i][m]);
            s0 += fmaxf(f.x + b0, 0.f);
            s1 += fmaxf(f.y + b1, 0.f);
        }
        atomicAdd(&smean[c0], s0);
        atomicAdd(&smean[c1], s1);
    }
    __syncthreads();
    if (tid < HID) atomicAdd(&g_meanv[b * HID + tid], smean[tid] * (1.0f / RR));
}

// ---------------- fc ---------------------------------------------------------
__global__ void k_fc(const float* __restrict__ fw, const float* __restrict__ fb,
                     float* __restrict__ out) {
    int b = blockIdx.x;
    __shared__ float m[HID];
    m[threadIdx.x] = g_meanv[b * HID + threadIdx.x];
    __syncthreads();
    if (threadIdx.x < OUTF) {
        float acc = fb[threadIdx.x];
#pragma unroll
        for (int f = 0; f < HID; f++)
            acc = fmaf(m[f], fw[f * OUTF + threadIdx.x], acc);
        out[b * OUTF + threadIdx.x] = acc;
    }
}

// ---------------- launch ------------------------------------------------------
extern "C" void kernel_launch(void* const* d_in, const int* in_sizes, int n_in,
                              void* d_out, int out_size) {
    const float* x   = (const float*)d_in[0];
    const int*   ei  = (const int*)  d_in[1];
    const float* c1w = (const float*)d_in[2];
    const float* c1b = (const float*)d_in[3];
    const float* c2w = (const float*)d_in[4];
    const float* c2b = (const float*)d_in[5];
    const float* g1w = (const float*)d_in[6];
    const float* g1b = (const float*)d_in[7];
    const float* g2w = (const float*)d_in[8];
    const float* g2b = (const float*)d_in[9];
    const float* fw  = (const float*)d_in[10];
    const float* fb  = (const float*)d_in[11];
    float* out = (float*)d_out;
    int etot = in_sizes[1] / 2;

    k_zero<<<1, RR>>>();
    k_count<<<ESING / 256, 256>>>(ei, etot);
    k_scan<<<1, RR>>>();
    k_fill<<<ESING / 256, 256>>>(ei, etot);
    k_conv1<<<dim3(T1 / 256, BATCH), 256>>>(x, c1w, c1b);
    k_conv2<<<dim3(RR / 256, BATCH), 512>>>(c2w, c2b);
    k_agg32<<<NNODES / 8, 256>>>();
    k_gemm1<<<NNODES / 128, 256>>>(g1w, g1b);
    k_agg128<<<NNODES / 8, 256>>>();
    k_gemm2m<<<NNODES / 128, 256>>>(g2w, g2b);
    k_fc<<<BATCH, HID>>>(fw, fb, out);
}